// round 15
// baseline (speedup 1.0000x reference)
#include <cuda_runtime.h>
#include <math.h>

#define EPSF 1e-5f

// ---------------- scratch arena ----------------
__device__ float g_scratch[27574472];

__host__ __device__ constexpr int clog2(int x) { int r = 0; while ((1 << r) < x) r++; return r; }

// ---------------- block reduction (blockDim.x == 256) ----------------
__device__ __forceinline__ void reduce2(float& s, float& s2) {
    __shared__ float rA[256];
    __shared__ float rB[256];
    __syncthreads();
    int t = threadIdx.x;
    rA[t] = s; rB[t] = s2;
    __syncthreads();
    for (int off = 128; off > 0; off >>= 1) {
        if (t < off) { rA[t] += rA[t + off]; rB[t] += rB[t + off]; }
        __syncthreads();
    }
    s = rA[0]; s2 = rB[0];
}

// ---------------- tf32 helpers ----------------
__device__ __forceinline__ unsigned int f2tf32(float f) {
    unsigned int u;
    asm("cvt.rna.tf32.f32 %0, %1;" : "=r"(u) : "f"(f));
    return u;
}

__device__ __forceinline__ void mma_tf32(float c[4], const unsigned int a[4],
                                         unsigned int b0, unsigned int b1) {
    asm volatile(
        "mma.sync.aligned.m16n8k8.row.col.f32.tf32.tf32.f32 "
        "{%0,%1,%2,%3}, {%4,%5,%6,%7}, {%8,%9}, {%0,%1,%2,%3};\n"
        : "+f"(c[0]), "+f"(c[1]), "+f"(c[2]), "+f"(c[3])
        : "r"(a[0]), "r"(a[1]), "r"(a[2]), "r"(a[3]), "r"(b0), "r"(b1));
}

// ---------------- merged weight repack + Bcat (one launch, grid 512) ----------------
template<int C_IN, int C_OUT>
__device__ __forceinline__ void repack_enc(int idx, const float* __restrict__ w,
                                           float* __restrict__ Wg) {
    if (idx >= 16 * C_IN * C_OUT) return;
    int o = idx % C_OUT; int rem = idx / C_OUT;
    int c = rem % C_IN;  int tap = rem / C_IN;
    int kh = tap & 3, kw = tap >> 2;
    Wg[idx] = w[((o * C_IN + c) * 4 + kh) * 4 + kw];
}

template<int C_IN, int C_OUT>
__device__ __forceinline__ void repack_dec(int idx, const float* __restrict__ w,
                                           float* __restrict__ Wg) {
    if (idx >= 16 * C_IN * C_OUT) return;
    int o = idx % C_OUT; int rem = idx / C_OUT;
    int c = rem % C_IN;  int rem2 = rem / C_IN;
    int g = rem2 & 3;    int pp = rem2 >> 2;
    int pa = pp >> 1, pb = pp & 1, ga = g >> 1, gb = g & 1;
    int kw0, kw1, kh0, kh1;
    if (pa == 0) { if (ga == 0) { kw0 = 0; kw1 = 1; } else { kw0 = 1; kw1 = 4; } }
    else         { if (ga == 0) { kw0 = 0; kw1 = 3; } else { kw0 = 3; kw1 = 4; } }
    if (pb == 0) { if (gb == 0) { kh0 = 0; kh1 = 1; } else { kh0 = 1; kh1 = 4; } }
    else         { if (gb == 0) { kh0 = 0; kh1 = 3; } else { kh0 = 3; kh1 = 4; } }
    float sum = 0.f;
    for (int kw = kw0; kw < kw1; kw++)
        for (int kh = kh0; kh < kh1; kh++)
            sum += w[(((size_t)o * C_IN + c) * 4 + kh) * 4 + kw];
    Wg[idx] = sum;
}

__global__ void k_repack_all(const float* __restrict__ c1w, const float* __restrict__ c2w,
                             const float* __restrict__ c3w, const float* __restrict__ d1w,
                             const float* __restrict__ d2w, const float* __restrict__ d3w,
                             const float* __restrict__ corew,
                             float* wgc1, float* wgc2, float* wgc3,
                             float* wgd1, float* wgd2, float* wgd3,
                             float* Bcat) {
    int idx = blockIdx.x * 256 + threadIdx.x;
    repack_enc<1, 16>(idx, c1w, wgc1);
    repack_enc<16, 32>(idx, c2w, wgc2);
    repack_enc<32, 64>(idx, c3w, wgc3);
    repack_dec<64, 32>(idx, d1w, wgd1);
    repack_dec<32, 16>(idx, d2w, wgd2);
    repack_dec<16, 1>(idx, d3w, wgd3);
    if (idx < 250 * 500) {
        int k = idx / 500, n = idx % 500;
        Bcat[idx] = (n < 250) ? corew[k * 250 + n] : corew[(k + 250) * 250 + (n - 250)];
    }
}

// ---------------- implicit-GEMM tf32 encoder conv (stride2, pad1, k4) ----------------
// MT m-subtiles per warp. Smem holds PRE-CONVERTED tf32; inner loop is LDS+MMA only.
template<int S_IN, int C_IN, int C_OUT, int MT, int ACT>
__global__ void __launch_bounds__(256)
k_conv_mma(const float* __restrict__ in, const float* __restrict__ Wg,
           const float* __restrict__ bias, float* __restrict__ out) {
    constexpr int S_OUT = S_IN / 2;
    constexpr int PS    = S_OUT * S_OUT;
    constexpr int PIX   = 128 * MT;
    constexpr int K_TOT = 16 * C_IN;
    constexpr int KC    = (K_TOT >= 32) ? 32 : K_TOT;
    constexpr int TPP   = 256 / PIX;
    constexpr int KEL   = KC / TPP;
    constexpr int NB    = (C_OUT < 8) ? 8 : C_OUT;
    constexpr int NT    = NB / 8;
    constexpr int AS    = PIX + 8;
    constexpr int BSs   = (NB % 32 == 0) ? NB + 8 : 40;
    constexpr int LC = clog2(C_IN), LPS = clog2(PS), LSO = clog2(S_OUT);
    __shared__ unsigned int As[KC][AS];
    __shared__ unsigned int Bs[KC][BSs];
    int tid = threadIdx.x;
    int warp = tid >> 5, lane = tid & 31, gid = lane >> 2, tig = lane & 3;
    int p_loc = tid % PIX;
    int koff  = (tid / PIX) * KEL;
    int m0 = blockIdx.x * PIX;
    int p_glob = m0 + p_loc;
    int n = p_glob >> LPS;
    int l = p_glob & (PS - 1);
    int a = l >> LSO, b = l & (S_OUT - 1);
    const float* inb = in + (size_t)n * S_IN * S_IN * C_IN;
    float acc[MT][NT][4];
    #pragma unroll
    for (int mt = 0; mt < MT; mt++)
        #pragma unroll
        for (int i = 0; i < NT; i++)
            { acc[mt][i][0] = acc[mt][i][1] = acc[mt][i][2] = acc[mt][i][3] = 0.f; }

    for (int k0 = 0; k0 < K_TOT; k0 += KC) {
        // A staging (implicit im2col, pre-converted to tf32)
        if constexpr (C_IN >= 4) {
            #pragma unroll
            for (int j = 0; j < KEL; j += 4) {
                int k = k0 + koff + j;
                int tap = k >> LC;
                int c0  = k & (C_IN - 1);
                int u = 2 * a - 1 + (tap >> 2);
                int v = 2 * b - 1 + (tap & 3);
                bool ok = (u >= 0) && (u < S_IN) && (v >= 0) && (v < S_IN);
                float4 xv = ok ? *reinterpret_cast<const float4*>(
                                    inb + ((size_t)u * S_IN + v) * C_IN + c0)
                               : make_float4(0.f, 0.f, 0.f, 0.f);
                As[koff + j + 0][p_loc] = f2tf32(xv.x); As[koff + j + 1][p_loc] = f2tf32(xv.y);
                As[koff + j + 2][p_loc] = f2tf32(xv.z); As[koff + j + 3][p_loc] = f2tf32(xv.w);
            }
        } else {
            #pragma unroll
            for (int j = 0; j < KEL; j++) {
                int k = k0 + koff + j;
                int tap = k >> LC;
                int c = k & (C_IN - 1);
                int u = 2 * a - 1 + (tap >> 2);
                int v = 2 * b - 1 + (tap & 3);
                bool ok = (u >= 0) && (u < S_IN) && (v >= 0) && (v < S_IN);
                As[koff + j][p_loc] = f2tf32(ok ? inb[((size_t)u * S_IN + v) * C_IN + c] : 0.f);
            }
        }
        // B staging (pre-converted)
        for (int idx = tid; idx < KC * NB; idx += 256) {
            int kk = idx / NB, o = idx % NB;
            Bs[kk][o] = f2tf32((o < C_OUT) ? Wg[(size_t)(k0 + kk) * C_OUT + o] : 0.f);
        }
        __syncthreads();
        #pragma unroll
        for (int ks = 0; ks < KC; ks += 8) {
            unsigned int bf[NT][2];
            #pragma unroll
            for (int nt = 0; nt < NT; nt++) {
                bf[nt][0] = Bs[ks + tig][nt * 8 + gid];
                bf[nt][1] = Bs[ks + tig + 4][nt * 8 + gid];
            }
            #pragma unroll
            for (int mt = 0; mt < MT; mt++) {
                unsigned int af[4];
                int mb = warp * 16 * MT + mt * 16 + gid;
                af[0] = As[ks + tig][mb];
                af[1] = As[ks + tig][mb + 8];
                af[2] = As[ks + tig + 4][mb];
                af[3] = As[ks + tig + 4][mb + 8];
                #pragma unroll
                for (int nt = 0; nt < NT; nt++)
                    mma_tf32(acc[mt][nt], af, bf[nt][0], bf[nt][1]);
            }
        }
        __syncthreads();
    }
    #pragma unroll
    for (int mt = 0; mt < MT; mt++) {
        int pixA = m0 + warp * 16 * MT + mt * 16 + gid;
        int pixB = pixA + 8;
        float* oA = out + (size_t)pixA * C_OUT;
        float* oB = out + (size_t)pixB * C_OUT;
        #pragma unroll
        for (int nt = 0; nt < NT; nt++) {
            int o = nt * 8 + tig * 2;
            if (o < C_OUT) {
                oA[o]     = acc[mt][nt][0] + bias[o];
                oA[o + 1] = acc[mt][nt][1] + bias[o + 1];
                oB[o]     = acc[mt][nt][2] + bias[o];
                oB[o + 1] = acc[mt][nt][3] + bias[o + 1];
            }
        }
    }
}

// ---------------- implicit-GEMM tf32 decoder deconv (up4+conv, 4x FLOP-reduced) ----------------
// One output-parity plane per blockIdx.y. MT m-subtiles per warp. ACT: 0 raw, 2 sigmoid.
template<int S_IN, int C_IN, int C_OUT, int MT, int ACT>
__global__ void __launch_bounds__(256)
k_deconv_mma(const float* __restrict__ in, const float* __restrict__ Wg,
             const float* __restrict__ bias, float* __restrict__ out) {
    constexpr int S_OUT = 2 * S_IN;
    constexpr int PS    = S_IN * S_IN;
    constexpr int PIX   = 128 * MT;
    constexpr int K_TOT = 4 * C_IN;
    constexpr int KC    = (K_TOT >= 32) ? 32 : K_TOT;
    constexpr int TPP   = 256 / PIX;
    constexpr int KEL   = KC / TPP;
    constexpr int NB    = (C_OUT < 8) ? 8 : C_OUT;
    constexpr int NT    = NB / 8;
    constexpr int AS    = PIX + 8;
    constexpr int BSs   = (NB % 32 == 0) ? NB + 8 : 40;
    constexpr int LC = clog2(C_IN), LPS = clog2(PS), LSI = clog2(S_IN);
    __shared__ unsigned int As[KC][AS];
    __shared__ unsigned int Bs[KC][BSs];
    int tid = threadIdx.x;
    int warp = tid >> 5, lane = tid & 31, gid = lane >> 2, tig = lane & 3;
    int pp = blockIdx.y;
    int pa = pp >> 1, pb = pp & 1;
    const float* Wp = Wg + (size_t)pp * 4 * C_IN * C_OUT;
    int p_loc = tid % PIX;
    int koff  = (tid / PIX) * KEL;
    int m0 = blockIdx.x * PIX;
    int p_glob = m0 + p_loc;
    int n = p_glob >> LPS;
    int l = p_glob & (PS - 1);
    int ma = l >> LSI, mb2 = l & (S_IN - 1);
    const float* inb = in + (size_t)n * S_IN * S_IN * C_IN;
    float acc[MT][NT][4];
    #pragma unroll
    for (int mt = 0; mt < MT; mt++)
        #pragma unroll
        for (int i = 0; i < NT; i++)
            { acc[mt][i][0] = acc[mt][i][1] = acc[mt][i][2] = acc[mt][i][3] = 0.f; }

    for (int k0 = 0; k0 < K_TOT; k0 += KC) {
        #pragma unroll
        for (int j = 0; j < KEL; j += 4) {
            int k = k0 + koff + j;                 // C_IN >= 16: groups of 4 stay in-group
            int g  = k >> LC;
            int c0 = k & (C_IN - 1);
            int su = (g & 2) ? (pa ? ma + 1 : ma) : (pa ? ma : ma - 1);
            int sv = (g & 1) ? (pb ? mb2 + 1 : mb2) : (pb ? mb2 : mb2 - 1);
            bool ok = (su >= 0) && (su < S_IN) && (sv >= 0) && (sv < S_IN);
            float4 xv = ok ? *reinterpret_cast<const float4*>(
                                inb + ((size_t)su * S_IN + sv) * C_IN + c0)
                           : make_float4(0.f, 0.f, 0.f, 0.f);
            As[koff + j + 0][p_loc] = f2tf32(xv.x); As[koff + j + 1][p_loc] = f2tf32(xv.y);
            As[koff + j + 2][p_loc] = f2tf32(xv.z); As[koff + j + 3][p_loc] = f2tf32(xv.w);
        }
        for (int idx = tid; idx < KC * NB; idx += 256) {
            int kk = idx / NB, o = idx % NB;
            Bs[kk][o] = f2tf32((o < C_OUT) ? Wp[(size_t)(k0 + kk) * C_OUT + o] : 0.f);
        }
        __syncthreads();
        #pragma unroll
        for (int ks = 0; ks < KC; ks += 8) {
            unsigned int bf[NT][2];
            #pragma unroll
            for (int nt = 0; nt < NT; nt++) {
                bf[nt][0] = Bs[ks + tig][nt * 8 + gid];
                bf[nt][1] = Bs[ks + tig + 4][nt * 8 + gid];
            }
            #pragma unroll
            for (int mt = 0; mt < MT; mt++) {
                unsigned int af[4];
                int mrow = warp * 16 * MT + mt * 16 + gid;
                af[0] = As[ks + tig][mrow];
                af[1] = As[ks + tig][mrow + 8];
                af[2] = As[ks + tig + 4][mrow];
                af[3] = As[ks + tig + 4][mrow + 8];
                #pragma unroll
                for (int nt = 0; nt < NT; nt++)
                    mma_tf32(acc[mt][nt], af, bf[nt][0], bf[nt][1]);
            }
        }
        __syncthreads();
    }
    // epilogue: map plane pixel -> (n, a=2ma+pa, b=2mb+pb)
    #pragma unroll
    for (int mt = 0; mt < MT; mt++) {
        #pragma unroll
        for (int half = 0; half < 2; half++) {
            int pix = m0 + warp * 16 * MT + mt * 16 + gid + half * 8;
            int nE = pix >> LPS;
            int lE = pix & (PS - 1);
            int aE = 2 * (lE >> LSI) + pa;
            int bE = 2 * (lE & (S_IN - 1)) + pb;
            float* op = out + (((size_t)nE * S_OUT + aE) * S_OUT + bE) * C_OUT;
            if constexpr (C_OUT == 1) {
                if (tig == 0) {
                    float v = acc[mt][0][half * 2] + bias[0];
                    op[0] = (ACT == 2) ? (1.f / (1.f + expf(-v))) : v;
                }
            } else {
                #pragma unroll
                for (int nt = 0; nt < NT; nt++) {
                    int o = nt * 8 + tig * 2;
                    op[o]     = acc[mt][nt][half * 2 + 0] + bias[o];
                    op[o + 1] = acc[mt][nt][half * 2 + 1] + bias[o + 1];
                }
            }
        }
    }
}

// ---------------- tf32 tensor-core split-K GEMM (64x64 tile, pre-converted smem) ----------------
__global__ void k_gemm_tc(const float* __restrict__ A, const float* __restrict__ B,
                          const float* __restrict__ bias, float* __restrict__ C,
                          int M, int N, int K, int ksteps_split) {
    __shared__ unsigned int As[16][72];
    __shared__ unsigned int Bs[16][72];
    int tid = threadIdx.x;
    int warp = tid >> 5, lane = tid & 31;
    int gid = lane >> 2, tig = lane & 3;
    int wm = warp >> 1, wn = warp & 1;
    int n0 = blockIdx.x * 64, m0 = blockIdx.y * 64;
    int k_begin = blockIdx.z * ksteps_split * 16;
    int k_end = min(K, k_begin + ksteps_split * 16);
    float c[4][4] = {};
    for (int k0 = k_begin; k0 < k_end; k0 += 16) {
        #pragma unroll
        for (int r = 0; r < 4; r++) {
            int idx = tid + r * 256;
            int mm = idx >> 4, kk = idx & 15;
            int gm = m0 + mm, gk = k0 + kk;
            As[kk][mm] = f2tf32((gm < M && gk < K) ? A[(size_t)gm * K + gk] : 0.f);
            int kk2 = idx >> 6, nn = idx & 63;
            int gk2 = k0 + kk2, gn = n0 + nn;
            Bs[kk2][nn] = f2tf32((gk2 < K && gn < N) ? B[(size_t)gk2 * N + gn] : 0.f);
        }
        __syncthreads();
        #pragma unroll
        for (int ks = 0; ks < 16; ks += 8) {
            unsigned int a[4];
            int mb = wm * 16 + gid;
            a[0] = As[ks + tig][mb];
            a[1] = As[ks + tig][mb + 8];
            a[2] = As[ks + tig + 4][mb];
            a[3] = As[ks + tig + 4][mb + 8];
            #pragma unroll
            for (int nt = 0; nt < 4; nt++) {
                int nb = wn * 32 + nt * 8 + gid;
                unsigned int b0 = Bs[ks + tig][nb];
                unsigned int b1 = Bs[ks + tig + 4][nb];
                mma_tf32(c[nt], a, b0, b1);
            }
        }
        __syncthreads();
    }
    float* Cw = C + (size_t)blockIdx.z * M * N;
    int mA = m0 + wm * 16 + gid;
    int mB = mA + 8;
    #pragma unroll
    for (int nt = 0; nt < 4; nt++) {
        int n = n0 + wn * 32 + nt * 8 + tig * 2;
        if (n < N) {
            float bb0 = bias ? bias[n] : 0.f;
            float bb1 = (n + 1 < N && bias) ? bias[n + 1] : 0.f;
            if (mA < M) {
                Cw[(size_t)mA * N + n] = c[nt][0] + bb0;
                if (n + 1 < N) Cw[(size_t)mA * N + n + 1] = c[nt][1] + bb1;
            }
            if (mB < M) {
                Cw[(size_t)mB * N + n] = c[nt][2] + bb0;
                if (n + 1 < N) Cw[(size_t)mB * N + n + 1] = c[nt][3] + bb1;
            }
        }
    }
}

// ---------------- split-K reduce + bias + optional row-LN + act (any N) ----------------
__global__ void k_reduce_ln(const float* __restrict__ part, const float* __restrict__ bias,
                            float* __restrict__ out, int M, int N, int nsplit, int act) {
    int r = blockIdx.x;
    float s = 0.f, s2 = 0.f;
    for (int c = threadIdx.x; c < N; c += 256) {
        float v = bias ? bias[c] : 0.f;
        for (int z = 0; z < nsplit; z++) v += part[((size_t)z * M + r) * N + c];
        out[(size_t)r * N + c] = v;
        s += v; s2 += v * v;
    }
    if (act < 0) return;
    reduce2(s, s2);
    float mean = s / N, var = s2 / N - mean * mean, rsg = rsqrtf(var + EPSF);
    for (int c = threadIdx.x; c < N; c += 256) {
        float v = (out[(size_t)r * N + c] - mean) * rsg;
        out[(size_t)r * N + c] = (act == 0) ? (v > 0.f ? v : expm1f(v)) : (v > 0.f ? v : 0.f);
    }
}

// ---------------- per-row layernorm + act, in-place, float4 (N % 1024 == 0) ----------------
__global__ void k_ln_act(float* __restrict__ X, int N, int act) {
    int r = blockIdx.x;
    float4* x = reinterpret_cast<float4*>(X + (size_t)r * N);
    int n4 = N >> 2;
    float s = 0.f, s2 = 0.f;
    for (int c = threadIdx.x; c < n4; c += 256) {
        float4 v = x[c];
        s  += v.x + v.y + v.z + v.w;
        s2 += v.x * v.x + v.y * v.y + v.z * v.z + v.w * v.w;
    }
    reduce2(s, s2);
    float mean = s / N, var = s2 / N - mean * mean, rsg = rsqrtf(var + EPSF);
    for (int c = threadIdx.x; c < n4; c += 256) {
        float4 v = x[c];
        float a0 = (v.x - mean) * rsg, a1 = (v.y - mean) * rsg;
        float a2 = (v.z - mean) * rsg, a3 = (v.w - mean) * rsg;
        if (act == 0) {
            v.x = a0 > 0.f ? a0 : expm1f(a0); v.y = a1 > 0.f ? a1 : expm1f(a1);
            v.z = a2 > 0.f ? a2 : expm1f(a2); v.w = a3 > 0.f ? a3 : expm1f(a3);
        } else {
            v.x = a0 > 0.f ? a0 : 0.f; v.y = a1 > 0.f ? a1 : 0.f;
            v.z = a2 > 0.f ? a2 : 0.f; v.w = a3 > 0.f ? a3 : 0.f;
        }
        x[c] = v;
    }
}

// ---------------- core rows ----------------
__global__ void k_core(const float* __restrict__ AB, const float* __restrict__ bias,
                       float* __restrict__ core) {
    int r = blockIdx.x;
    int jj = r % 7; int fi = r / 7; int i = fi % 8; int bi = fi / 8;
    int j = (jj < i) ? jj : jj + 1;
    const float* ar = AB + (size_t)fi * 500;
    const float* br = AB + (size_t)(bi * 8 + j) * 500 + 250;
    __shared__ float row[256];
    float s = 0.f, s2 = 0.f;
    for (int c = threadIdx.x; c < 250; c += 256) {
        float v = ar[c] + br[c] + bias[c];
        row[c] = v; s += v; s2 += v * v;
    }
    reduce2(s, s2);
    float mean = s / 250.f, var = s2 / 250.f - mean * mean, rsg = rsqrtf(var + EPSF);
    float* o = core + (size_t)r * 250;
    for (int c = threadIdx.x; c < 250; c += 256) {
        float v = (row[c] - mean) * rsg;
        o[c] = v > 0.f ? v : 0.f;
    }
}

// ---------------- fused att ----------------
__global__ void k_att2(const float* __restrict__ part, const float* __restrict__ b1,
                       const float* __restrict__ w2, const float* __restrict__ b2,
                       float* __restrict__ att, int M, int nsplit) {
    __shared__ float row[128];
    int r = blockIdx.x;
    float s = 0.f, s2 = 0.f;
    for (int c = threadIdx.x; c < 100; c += 256) {
        float v = b1[c];
        for (int z = 0; z < nsplit; z++) v += part[((size_t)z * M + r) * 100 + c];
        row[c] = v; s += v; s2 += v * v;
    }
    reduce2(s, s2);
    float mean = s / 100.f, var = s2 / 100.f - mean * mean, rsg = rsqrtf(var + EPSF);
    float d = 0.f;
    for (int c = threadIdx.x; c < 100; c += 256)
        d += tanhf((row[c] - mean) * rsg) * w2[c];
    float dummy = 0.f;
    reduce2(d, dummy);
    if (threadIdx.x == 0) att[r] = 1.f / (1.f + expf(-(d + b2[0])));
}

// ---------------- fused effect + concat ----------------
__global__ void k_total2(const float* __restrict__ s1, const float* __restrict__ ctx,
                         const float* __restrict__ att, const float* __restrict__ hf,
                         float* __restrict__ total) {
    int idx = blockIdx.x * 256 + threadIdx.x;
    if (idx >= 384 * 1012) return;
    int n = idx / 1012, c = idx % 1012;
    float v;
    if (c < 250) v = s1[n * 250 + c];
    else if (c < 500) {
        int cc = c - 250;
        float s = 0.f;
        #pragma unroll
        for (int jj = 0; jj < 7; jj++)
            s += ctx[((size_t)n * 7 + jj) * 250 + cc] * att[n * 7 + jj];
        v = s;
    } else v = hf[n * 512 + (c - 500)];
    total[idx] = v;
}

// ---------------- fused state head ----------------
__global__ void k_state2(const float* __restrict__ part, const float* __restrict__ bias,
                         float* __restrict__ xr, float* __restrict__ so, int nsplit) {
    __shared__ float row[256];
    int r = blockIdx.x;
    float s = 0.f, s2 = 0.f;
    for (int c = threadIdx.x; c < 250; c += 256) {
        float v = bias[c];
        for (int z = 0; z < nsplit; z++) v += part[((size_t)z * 384 + r) * 250 + c];
        row[c] = v; s += v; s2 += v * v;
    }
    reduce2(s, s2);
    float mean = s / 250.f, var = s2 / 250.f - mean * mean, rsg = rsqrtf(var + EPSF);
    for (int c = threadIdx.x; c < 250; c += 256) {
        float v = row[c];
        xr[(size_t)r * 250 + c] = 1.f / (1.f + expf(-((v - mean) * rsg)));
        so[(size_t)r * 250 + c] = 1.f / (1.f + expf(-v));
    }
}

// ---------------- launch ----------------
extern "C" void kernel_launch(void* const* d_in, const int* in_sizes, int n_in,
                              void* d_out, int out_size) {
    const float* x     = (const float*)d_in[0];
    const float* state = (const float*)d_in[1];
    const float* c1w   = (const float*)d_in[2];  const float* c1b  = (const float*)d_in[3];
    const float* c2w   = (const float*)d_in[4];  const float* c2b  = (const float*)d_in[5];
    const float* c3w   = (const float*)d_in[6];  const float* c3b  = (const float*)d_in[7];
    const float* efcw  = (const float*)d_in[8];  const float* efcb = (const float*)d_in[9];
    const float* rencw = (const float*)d_in[10]; const float* rencb= (const float*)d_in[11];
    const float* corew = (const float*)d_in[12]; const float* coreb= (const float*)d_in[13];
    const float* ctxw  = (const float*)d_in[14]; const float* ctxb = (const float*)d_in[15];
    const float* att1w = (const float*)d_in[16]; const float* att1b= (const float*)d_in[17];
    const float* att2w = (const float*)d_in[18]; const float* att2b= (const float*)d_in[19];
    const float* outw  = (const float*)d_in[20]; const float* outb = (const float*)d_in[21];
    const float* dfc1w = (const float*)d_in[22]; const float* dfc1b= (const float*)d_in[23];
    const float* dfc2w = (const float*)d_in[24]; const float* dfc2b= (const float*)d_in[25];
    const float* d1w   = (const float*)d_in[26]; const float* d1b  = (const float*)d_in[27];
    const float* d2w   = (const float*)d_in[28]; const float* d2b  = (const float*)d_in[29];
    const float* d3w   = (const float*)d_in[30]; const float* d3b  = (const float*)d_in[31];
    float* out = (float*)d_out;

    float* S = nullptr;
    cudaGetSymbolAddress((void**)&S, g_scratch);
    float* h1   = S;                    // 6291456 (reused as dfc2 split scratch)
    float* h2   = h1  + 6291456;        // 3145728
    float* h3   = h2  + 3145728;        // 1572864
    float* hf   = h3  + 1572864;        // 196608
    float* s1   = hf  + 196608;         // 96000
    float* AB   = s1  + 96000;          // 192000
    float* core = AB  + 192000;         // 672000
    float* ctx  = core+ 672000;         // 672000
    float* att  = ctx + 672000;         // 2688
    float* tot  = att + 2688;           // 388608
    float* xr   = tot + 388608;         // 96000
    float* d1   = xr  + 96000;          // 196608
    float* d2   = d1  + 196608;         // 1572864
    float* dd1  = d2  + 1572864;        // 3145728
    float* dd2  = dd1 + 3145728;        // 6291456
    float* Bcat = dd2 + 6291456;        // 125000
    float* part = Bcat+ 125000;         // 1572864
    float* wgc1 = part+ 1572864;        // 256
    float* wgc2 = wgc1+ 256;            // 8192
    float* wgc3 = wgc2+ 8192;           // 32768
    float* wgd1 = wgc3+ 32768;          // 32768
    float* wgd2 = wgd1+ 32768;          // 8192
    float* wgd3 = wgd2+ 8192;           // 256

    const float* NOB = nullptr;

    // ---- merged weight repack + Bcat (one launch) ----
    k_repack_all<<<512, 256>>>(c1w, c2w, c3w, d1w, d2w, d3w, corew,
                               wgc1, wgc2, wgc3, wgd1, wgd2, wgd3, Bcat);

    // ---- encoder (implicit-GEMM tf32 convs + LN passes) ----
    k_conv_mma<64,1,16,2,0><<<1536, 256>>>(x, wgc1, c1b, h1);
    k_ln_act<<<384, 256>>>(h1, 16384, 0);
    k_conv_mma<32,16,32,2,0><<<384, 256>>>(h1, wgc2, c2b, h2);
    k_ln_act<<<384, 256>>>(h2, 8192, 0);
    k_conv_mma<16,32,64,1,0><<<192, 256>>>(h2, wgc3, c3b, h3);
    k_ln_act<<<384, 256>>>(h3, 4096, 0);
    { dim3 g(8, 6, 8); k_gemm_tc<<<g, 256>>>(h3, efcw, NOB, part, 384, 512, 4096, 32); }
    k_reduce_ln<<<384, 256>>>(part, efcb, hf, 384, 512, 8, 0);

    // ---- recurrent / pairwise ----
    { dim3 g(4, 6, 4); k_gemm_tc<<<g, 256>>>(state, rencw, NOB, part, 384, 250, 250, 4); }
    k_reduce_ln<<<384, 256>>>(part, rencb, s1, 384, 250, 4, 1);
    { dim3 g(8, 6, 4); k_gemm_tc<<<g, 256>>>(s1, Bcat, NOB, part, 384, 500, 250, 4); }
    k_reduce_ln<<<384, 256>>>(part, NOB, AB, 384, 500, 4, -1);
    k_core<<<2688, 256>>>(AB, coreb, core);
    { dim3 g(4, 42, 2); k_gemm_tc<<<g, 256>>>(core, ctxw, NOB, part, 2688, 250, 250, 8); }
    k_reduce_ln<<<2688, 256>>>(part, ctxb, ctx, 2688, 250, 2, 1);
    { dim3 g(2, 42, 4); k_gemm_tc<<<g, 256>>>(core, att1w, NOB, part, 2688, 100, 250, 4); }
    k_att2<<<2688, 256>>>(part, att1b, att2w, att2b, att, 2688, 4);
    k_total2<<<(388608 + 255) / 256, 256>>>(s1, ctx, att, hf, tot);
    { dim3 g(4, 6, 8); k_gemm_tc<<<g, 256>>>(tot, outw, NOB, part, 384, 250, 1012, 8); }
    k_state2<<<384, 256>>>(part, outb, xr, out + 384 * 4096, 8);

    // ---- decoder ----
    { dim3 g(8, 6, 4); k_gemm_tc<<<g, 256>>>(xr, dfc1w, NOB, part, 384, 512, 250, 4); }
    k_reduce_ln<<<384, 256>>>(part, dfc1b, d1, 384, 512, 4, 1);
    { dim3 g(64, 6, 2); k_gemm_tc<<<g, 256>>>(d1, dfc2w, NOB, h1, 384, 4096, 512, 16); }
    k_reduce_ln<<<384, 256>>>(h1, dfc2b, d2, 384, 4096, 2, 1);
    k_deconv_mma<8,64,32,2,0><<<dim3(96, 4), 256>>>(d2, wgd1, d1b, dd1);
    k_ln_act<<<384, 256>>>(dd1, 8192, 1);
    k_deconv_mma<16,32,16,2,0><<<dim3(384, 4), 256>>>(dd1, wgd2, d2b, dd2);
    k_ln_act<<<384, 256>>>(dd2, 16384, 1);
    k_deconv_mma<32,16,1,2,2><<<dim3(1536, 4), 256>>>(dd2, wgd3, d3b, out);
}

// round 16
// speedup vs baseline: 1.2117x; 1.2117x over previous
#include <cuda_runtime.h>
#include <math.h>

#define EPSF 1e-5f

// ---------------- scratch arena ----------------
__device__ float g_scratch[27574472];

__host__ __device__ constexpr int clog2(int x) { int r = 0; while ((1 << r) < x) r++; return r; }

// ---------------- block reduction (blockDim.x == 256) ----------------
__device__ __forceinline__ void reduce2(float& s, float& s2) {
    __shared__ float rA[256];
    __shared__ float rB[256];
    __syncthreads();
    int t = threadIdx.x;
    rA[t] = s; rB[t] = s2;
    __syncthreads();
    for (int off = 128; off > 0; off >>= 1) {
        if (t < off) { rA[t] += rA[t + off]; rB[t] += rB[t + off]; }
        __syncthreads();
    }
    s = rA[0]; s2 = rB[0];
}

// ---------------- tf32 helpers ----------------
__device__ __forceinline__ unsigned int f2tf32(float f) {
    unsigned int u;
    asm("cvt.rna.tf32.f32 %0, %1;" : "=r"(u) : "f"(f));
    return u;
}

__device__ __forceinline__ void mma_tf32(float c[4], const unsigned int a[4],
                                         unsigned int b0, unsigned int b1) {
    asm volatile(
        "mma.sync.aligned.m16n8k8.row.col.f32.tf32.tf32.f32 "
        "{%0,%1,%2,%3}, {%4,%5,%6,%7}, {%8,%9}, {%0,%1,%2,%3};\n"
        : "+f"(c[0]), "+f"(c[1]), "+f"(c[2]), "+f"(c[3])
        : "r"(a[0]), "r"(a[1]), "r"(a[2]), "r"(a[3]), "r"(b0), "r"(b1));
}

// ---------------- merged weight repack + Bcat (one launch, grid 512) ----------------
template<int C_IN, int C_OUT>
__device__ __forceinline__ void repack_enc(int idx, const float* __restrict__ w,
                                           float* __restrict__ Wg) {
    if (idx >= 16 * C_IN * C_OUT) return;
    int o = idx % C_OUT; int rem = idx / C_OUT;
    int c = rem % C_IN;  int tap = rem / C_IN;
    int kh = tap & 3, kw = tap >> 2;
    Wg[idx] = w[((o * C_IN + c) * 4 + kh) * 4 + kw];
}

template<int C_IN, int C_OUT>
__device__ __forceinline__ void repack_dec(int idx, const float* __restrict__ w,
                                           float* __restrict__ Wg) {
    if (idx >= 16 * C_IN * C_OUT) return;
    int o = idx % C_OUT; int rem = idx / C_OUT;
    int c = rem % C_IN;  int rem2 = rem / C_IN;
    int g = rem2 & 3;    int pp = rem2 >> 2;
    int pa = pp >> 1, pb = pp & 1, ga = g >> 1, gb = g & 1;
    int kw0, kw1, kh0, kh1;
    if (pa == 0) { if (ga == 0) { kw0 = 0; kw1 = 1; } else { kw0 = 1; kw1 = 4; } }
    else         { if (ga == 0) { kw0 = 0; kw1 = 3; } else { kw0 = 3; kw1 = 4; } }
    if (pb == 0) { if (gb == 0) { kh0 = 0; kh1 = 1; } else { kh0 = 1; kh1 = 4; } }
    else         { if (gb == 0) { kh0 = 0; kh1 = 3; } else { kh0 = 3; kh1 = 4; } }
    float sum = 0.f;
    for (int kw = kw0; kw < kw1; kw++)
        for (int kh = kh0; kh < kh1; kh++)
            sum += w[(((size_t)o * C_IN + c) * 4 + kh) * 4 + kw];
    Wg[idx] = sum;
}

__global__ void k_repack_all(const float* __restrict__ c1w, const float* __restrict__ c2w,
                             const float* __restrict__ c3w, const float* __restrict__ d1w,
                             const float* __restrict__ d2w, const float* __restrict__ d3w,
                             const float* __restrict__ corew,
                             float* wgc1, float* wgc2, float* wgc3,
                             float* wgd1, float* wgd2, float* wgd3,
                             float* Bcat) {
    int idx = blockIdx.x * 256 + threadIdx.x;
    repack_enc<1, 16>(idx, c1w, wgc1);
    repack_enc<16, 32>(idx, c2w, wgc2);
    repack_enc<32, 64>(idx, c3w, wgc3);
    repack_dec<64, 32>(idx, d1w, wgd1);
    repack_dec<32, 16>(idx, d2w, wgd2);
    repack_dec<16, 1>(idx, d3w, wgd3);
    if (idx < 250 * 500) {
        int k = idx / 500, n = idx % 500;
        Bcat[idx] = (n < 250) ? corew[k * 250 + n] : corew[(k + 250) * 250 + (n - 250)];
    }
}

// ---------------- implicit-GEMM tf32 encoder conv (stride2, pad1, k4) ----------------
// MT m-subtiles per warp (CTA covers 128*MT pixels). Conflict-free smem strides.
template<int S_IN, int C_IN, int C_OUT, int MT, int ACT>
__global__ void __launch_bounds__(256)
k_conv_mma(const float* __restrict__ in, const float* __restrict__ Wg,
           const float* __restrict__ bias, float* __restrict__ out) {
    constexpr int S_OUT = S_IN / 2;
    constexpr int PS    = S_OUT * S_OUT;
    constexpr int PIX   = 128 * MT;
    constexpr int K_TOT = 16 * C_IN;
    constexpr int KC    = (K_TOT >= 32) ? 32 : K_TOT;
    constexpr int TPP   = 256 / PIX;
    constexpr int KEL   = KC / TPP;
    constexpr int NB    = (C_OUT < 8) ? 8 : C_OUT;
    constexpr int NT    = NB / 8;
    constexpr int AS    = PIX + 8;
    constexpr int BSs   = (NB % 32 == 0) ? NB + 8 : 40;
    constexpr int LC = clog2(C_IN), LPS = clog2(PS), LSO = clog2(S_OUT);
    __shared__ float As[KC][AS];
    __shared__ float Bs[KC][BSs];
    int tid = threadIdx.x;
    int warp = tid >> 5, lane = tid & 31, gid = lane >> 2, tig = lane & 3;
    int p_loc = tid % PIX;
    int koff  = (tid / PIX) * KEL;
    int m0 = blockIdx.x * PIX;
    int p_glob = m0 + p_loc;
    int n = p_glob >> LPS;
    int l = p_glob & (PS - 1);
    int a = l >> LSO, b = l & (S_OUT - 1);
    const float* inb = in + (size_t)n * S_IN * S_IN * C_IN;
    float acc[MT][NT][4];
    #pragma unroll
    for (int mt = 0; mt < MT; mt++)
        #pragma unroll
        for (int i = 0; i < NT; i++)
            { acc[mt][i][0] = acc[mt][i][1] = acc[mt][i][2] = acc[mt][i][3] = 0.f; }

    for (int k0 = 0; k0 < K_TOT; k0 += KC) {
        // A staging (implicit im2col)
        if constexpr (C_IN >= 4) {
            #pragma unroll
            for (int j = 0; j < KEL; j += 4) {
                int k = k0 + koff + j;
                int tap = k >> LC;
                int c0  = k & (C_IN - 1);
                int u = 2 * a - 1 + (tap >> 2);
                int v = 2 * b - 1 + (tap & 3);
                bool ok = (u >= 0) && (u < S_IN) && (v >= 0) && (v < S_IN);
                float4 xv = ok ? *reinterpret_cast<const float4*>(
                                    inb + ((size_t)u * S_IN + v) * C_IN + c0)
                               : make_float4(0.f, 0.f, 0.f, 0.f);
                As[koff + j + 0][p_loc] = xv.x; As[koff + j + 1][p_loc] = xv.y;
                As[koff + j + 2][p_loc] = xv.z; As[koff + j + 3][p_loc] = xv.w;
            }
        } else {
            #pragma unroll
            for (int j = 0; j < KEL; j++) {
                int k = k0 + koff + j;
                int tap = k >> LC;
                int c = k & (C_IN - 1);
                int u = 2 * a - 1 + (tap >> 2);
                int v = 2 * b - 1 + (tap & 3);
                bool ok = (u >= 0) && (u < S_IN) && (v >= 0) && (v < S_IN);
                As[koff + j][p_loc] = ok ? inb[((size_t)u * S_IN + v) * C_IN + c] : 0.f;
            }
        }
        // B staging
        for (int idx = tid; idx < KC * NB; idx += 256) {
            int kk = idx / NB, o = idx % NB;
            Bs[kk][o] = (o < C_OUT) ? Wg[(size_t)(k0 + kk) * C_OUT + o] : 0.f;
        }
        __syncthreads();
        #pragma unroll
        for (int ks = 0; ks < KC; ks += 8) {
            unsigned int bf[NT][2];
            #pragma unroll
            for (int nt = 0; nt < NT; nt++) {
                bf[nt][0] = f2tf32(Bs[ks + tig][nt * 8 + gid]);
                bf[nt][1] = f2tf32(Bs[ks + tig + 4][nt * 8 + gid]);
            }
            #pragma unroll
            for (int mt = 0; mt < MT; mt++) {
                unsigned int af[4];
                int mb = warp * 16 * MT + mt * 16 + gid;
                af[0] = f2tf32(As[ks + tig][mb]);
                af[1] = f2tf32(As[ks + tig][mb + 8]);
                af[2] = f2tf32(As[ks + tig + 4][mb]);
                af[3] = f2tf32(As[ks + tig + 4][mb + 8]);
                #pragma unroll
                for (int nt = 0; nt < NT; nt++)
                    mma_tf32(acc[mt][nt], af, bf[nt][0], bf[nt][1]);
            }
        }
        __syncthreads();
    }
    #pragma unroll
    for (int mt = 0; mt < MT; mt++) {
        int pixA = m0 + warp * 16 * MT + mt * 16 + gid;
        int pixB = pixA + 8;
        float* oA = out + (size_t)pixA * C_OUT;
        float* oB = out + (size_t)pixB * C_OUT;
        #pragma unroll
        for (int nt = 0; nt < NT; nt++) {
            int o = nt * 8 + tig * 2;
            if (o < C_OUT) {
                oA[o]     = acc[mt][nt][0] + bias[o];
                oA[o + 1] = acc[mt][nt][1] + bias[o + 1];
                oB[o]     = acc[mt][nt][2] + bias[o];
                oB[o + 1] = acc[mt][nt][3] + bias[o + 1];
            }
        }
    }
}

// ---------------- implicit-GEMM tf32 decoder deconv (up4+conv, 4x FLOP-reduced) ----------------
// One output-parity plane per blockIdx.y. MT m-subtiles per warp. ACT: 0 raw, 2 sigmoid.
template<int S_IN, int C_IN, int C_OUT, int MT, int ACT>
__global__ void __launch_bounds__(256)
k_deconv_mma(const float* __restrict__ in, const float* __restrict__ Wg,
             const float* __restrict__ bias, float* __restrict__ out) {
    constexpr int S_OUT = 2 * S_IN;
    constexpr int PS    = S_IN * S_IN;
    constexpr int PIX   = 128 * MT;
    constexpr int K_TOT = 4 * C_IN;
    constexpr int KC    = (K_TOT >= 32) ? 32 : K_TOT;
    constexpr int TPP   = 256 / PIX;
    constexpr int KEL   = KC / TPP;
    constexpr int NB    = (C_OUT < 8) ? 8 : C_OUT;
    constexpr int NT    = NB / 8;
    constexpr int AS    = PIX + 8;
    constexpr int BSs   = (NB % 32 == 0) ? NB + 8 : 40;
    constexpr int LC = clog2(C_IN), LPS = clog2(PS), LSI = clog2(S_IN);
    __shared__ float As[KC][AS];
    __shared__ float Bs[KC][BSs];
    int tid = threadIdx.x;
    int warp = tid >> 5, lane = tid & 31, gid = lane >> 2, tig = lane & 3;
    int pp = blockIdx.y;
    int pa = pp >> 1, pb = pp & 1;
    const float* Wp = Wg + (size_t)pp * 4 * C_IN * C_OUT;
    int p_loc = tid % PIX;
    int koff  = (tid / PIX) * KEL;
    int m0 = blockIdx.x * PIX;
    int p_glob = m0 + p_loc;
    int n = p_glob >> LPS;
    int l = p_glob & (PS - 1);
    int ma = l >> LSI, mb2 = l & (S_IN - 1);
    const float* inb = in + (size_t)n * S_IN * S_IN * C_IN;
    float acc[MT][NT][4];
    #pragma unroll
    for (int mt = 0; mt < MT; mt++)
        #pragma unroll
        for (int i = 0; i < NT; i++)
            { acc[mt][i][0] = acc[mt][i][1] = acc[mt][i][2] = acc[mt][i][3] = 0.f; }

    for (int k0 = 0; k0 < K_TOT; k0 += KC) {
        #pragma unroll
        for (int j = 0; j < KEL; j += 4) {
            int k = k0 + koff + j;                 // C_IN >= 16: groups of 4 stay in-group
            int g  = k >> LC;
            int c0 = k & (C_IN - 1);
            int su = (g & 2) ? (pa ? ma + 1 : ma) : (pa ? ma : ma - 1);
            int sv = (g & 1) ? (pb ? mb2 + 1 : mb2) : (pb ? mb2 : mb2 - 1);
            bool ok = (su >= 0) && (su < S_IN) && (sv >= 0) && (sv < S_IN);
            float4 xv = ok ? *reinterpret_cast<const float4*>(
                                inb + ((size_t)su * S_IN + sv) * C_IN + c0)
                           : make_float4(0.f, 0.f, 0.f, 0.f);
            As[koff + j + 0][p_loc] = xv.x; As[koff + j + 1][p_loc] = xv.y;
            As[koff + j + 2][p_loc] = xv.z; As[koff + j + 3][p_loc] = xv.w;
        }
        for (int idx = tid; idx < KC * NB; idx += 256) {
            int kk = idx / NB, o = idx % NB;
            Bs[kk][o] = (o < C_OUT) ? Wp[(size_t)(k0 + kk) * C_OUT + o] : 0.f;
        }
        __syncthreads();
        #pragma unroll
        for (int ks = 0; ks < KC; ks += 8) {
            unsigned int bf[NT][2];
            #pragma unroll
            for (int nt = 0; nt < NT; nt++) {
                bf[nt][0] = f2tf32(Bs[ks + tig][nt * 8 + gid]);
                bf[nt][1] = f2tf32(Bs[ks + tig + 4][nt * 8 + gid]);
            }
            #pragma unroll
            for (int mt = 0; mt < MT; mt++) {
                unsigned int af[4];
                int mrow = warp * 16 * MT + mt * 16 + gid;
                af[0] = f2tf32(As[ks + tig][mrow]);
                af[1] = f2tf32(As[ks + tig][mrow + 8]);
                af[2] = f2tf32(As[ks + tig + 4][mrow]);
                af[3] = f2tf32(As[ks + tig + 4][mrow + 8]);
                #pragma unroll
                for (int nt = 0; nt < NT; nt++)
                    mma_tf32(acc[mt][nt], af, bf[nt][0], bf[nt][1]);
            }
        }
        __syncthreads();
    }
    // epilogue: map plane pixel -> (n, a=2ma+pa, b=2mb+pb)
    #pragma unroll
    for (int mt = 0; mt < MT; mt++) {
        #pragma unroll
        for (int half = 0; half < 2; half++) {
            int pix = m0 + warp * 16 * MT + mt * 16 + gid + half * 8;
            int nE = pix >> LPS;
            int lE = pix & (PS - 1);
            int aE = 2 * (lE >> LSI) + pa;
            int bE = 2 * (lE & (S_IN - 1)) + pb;
            float* op = out + (((size_t)nE * S_OUT + aE) * S_OUT + bE) * C_OUT;
            if constexpr (C_OUT == 1) {
                if (tig == 0) {
                    float v = acc[mt][0][half * 2] + bias[0];
                    op[0] = (ACT == 2) ? (1.f / (1.f + expf(-v))) : v;
                }
            } else {
                #pragma unroll
                for (int nt = 0; nt < NT; nt++) {
                    int o = nt * 8 + tig * 2;
                    op[o]     = acc[mt][nt][half * 2 + 0] + bias[o];
                    op[o + 1] = acc[mt][nt][half * 2 + 1] + bias[o + 1];
                }
            }
        }
    }
}

// ---------------- tf32 tensor-core split-K GEMM (64x64 tile, mma.m16n8k8) ----------------
__global__ void k_gemm_tc(const float* __restrict__ A, const float* __restrict__ B,
                          const float* __restrict__ bias, float* __restrict__ C,
                          int M, int N, int K, int ksteps_split) {
    __shared__ float As[16][72];
    __shared__ float Bs[16][72];
    int tid = threadIdx.x;
    int warp = tid >> 5, lane = tid & 31;
    int gid = lane >> 2, tig = lane & 3;
    int wm = warp >> 1, wn = warp & 1;
    int n0 = blockIdx.x * 64, m0 = blockIdx.y * 64;
    int k_begin = blockIdx.z * ksteps_split * 16;
    int k_end = min(K, k_begin + ksteps_split * 16);
    float c[4][4] = {};
    for (int k0 = k_begin; k0 < k_end; k0 += 16) {
        #pragma unroll
        for (int r = 0; r < 4; r++) {
            int idx = tid + r * 256;
            int mm = idx >> 4, kk = idx & 15;
            int gm = m0 + mm, gk = k0 + kk;
            As[kk][mm] = (gm < M && gk < K) ? A[(size_t)gm * K + gk] : 0.f;
            int kk2 = idx >> 6, nn = idx & 63;
            int gk2 = k0 + kk2, gn = n0 + nn;
            Bs[kk2][nn] = (gk2 < K && gn < N) ? B[(size_t)gk2 * N + gn] : 0.f;
        }
        __syncthreads();
        #pragma unroll
        for (int ks = 0; ks < 16; ks += 8) {
            unsigned int a[4];
            int mb = wm * 16 + gid;
            a[0] = f2tf32(As[ks + tig][mb]);
            a[1] = f2tf32(As[ks + tig][mb + 8]);
            a[2] = f2tf32(As[ks + tig + 4][mb]);
            a[3] = f2tf32(As[ks + tig + 4][mb + 8]);
            #pragma unroll
            for (int nt = 0; nt < 4; nt++) {
                int nb = wn * 32 + nt * 8 + gid;
                unsigned int b0 = f2tf32(Bs[ks + tig][nb]);
                unsigned int b1 = f2tf32(Bs[ks + tig + 4][nb]);
                mma_tf32(c[nt], a, b0, b1);
            }
        }
        __syncthreads();
    }
    float* Cw = C + (size_t)blockIdx.z * M * N;
    int mA = m0 + wm * 16 + gid;
    int mB = mA + 8;
    #pragma unroll
    for (int nt = 0; nt < 4; nt++) {
        int n = n0 + wn * 32 + nt * 8 + tig * 2;
        if (n < N) {
            float bb0 = bias ? bias[n] : 0.f;
            float bb1 = (n + 1 < N && bias) ? bias[n + 1] : 0.f;
            if (mA < M) {
                Cw[(size_t)mA * N + n] = c[nt][0] + bb0;
                if (n + 1 < N) Cw[(size_t)mA * N + n + 1] = c[nt][1] + bb1;
            }
            if (mB < M) {
                Cw[(size_t)mB * N + n] = c[nt][2] + bb0;
                if (n + 1 < N) Cw[(size_t)mB * N + n + 1] = c[nt][3] + bb1;
            }
        }
    }
}

// ---------------- split-K reduce + bias + optional row-LN + act (any N) ----------------
__global__ void k_reduce_ln(const float* __restrict__ part, const float* __restrict__ bias,
                            float* __restrict__ out, int M, int N, int nsplit, int act) {
    int r = blockIdx.x;
    float s = 0.f, s2 = 0.f;
    for (int c = threadIdx.x; c < N; c += 256) {
        float v = bias ? bias[c] : 0.f;
        for (int z = 0; z < nsplit; z++) v += part[((size_t)z * M + r) * N + c];
        out[(size_t)r * N + c] = v;
        s += v; s2 += v * v;
    }
    if (act < 0) return;
    reduce2(s, s2);
    float mean = s / N, var = s2 / N - mean * mean, rsg = rsqrtf(var + EPSF);
    for (int c = threadIdx.x; c < N; c += 256) {
        float v = (out[(size_t)r * N + c] - mean) * rsg;
        out[(size_t)r * N + c] = (act == 0) ? (v > 0.f ? v : expm1f(v)) : (v > 0.f ? v : 0.f);
    }
}

// ---------------- per-row layernorm + act, in-place, float4 (N % 1024 == 0) ----------------
__global__ void k_ln_act(float* __restrict__ X, int N, int act) {
    int r = blockIdx.x;
    float4* x = reinterpret_cast<float4*>(X + (size_t)r * N);
    int n4 = N >> 2;
    float s = 0.f, s2 = 0.f;
    for (int c = threadIdx.x; c < n4; c += 256) {
        float4 v = x[c];
        s  += v.x + v.y + v.z + v.w;
        s2 += v.x * v.x + v.y * v.y + v.z * v.z + v.w * v.w;
    }
    reduce2(s, s2);
    float mean = s / N, var = s2 / N - mean * mean, rsg = rsqrtf(var + EPSF);
    for (int c = threadIdx.x; c < n4; c += 256) {
        float4 v = x[c];
        float a0 = (v.x - mean) * rsg, a1 = (v.y - mean) * rsg;
        float a2 = (v.z - mean) * rsg, a3 = (v.w - mean) * rsg;
        if (act == 0) {
            v.x = a0 > 0.f ? a0 : expm1f(a0); v.y = a1 > 0.f ? a1 : expm1f(a1);
            v.z = a2 > 0.f ? a2 : expm1f(a2); v.w = a3 > 0.f ? a3 : expm1f(a3);
        } else {
            v.x = a0 > 0.f ? a0 : 0.f; v.y = a1 > 0.f ? a1 : 0.f;
            v.z = a2 > 0.f ? a2 : 0.f; v.w = a3 > 0.f ? a3 : 0.f;
        }
        x[c] = v;
    }
}

// ---------------- core rows ----------------
__global__ void k_core(const float* __restrict__ AB, const float* __restrict__ bias,
                       float* __restrict__ core) {
    int r = blockIdx.x;
    int jj = r % 7; int fi = r / 7; int i = fi % 8; int bi = fi / 8;
    int j = (jj < i) ? jj : jj + 1;
    const float* ar = AB + (size_t)fi * 500;
    const float* br = AB + (size_t)(bi * 8 + j) * 500 + 250;
    __shared__ float row[256];
    float s = 0.f, s2 = 0.f;
    for (int c = threadIdx.x; c < 250; c += 256) {
        float v = ar[c] + br[c] + bias[c];
        row[c] = v; s += v; s2 += v * v;
    }
    reduce2(s, s2);
    float mean = s / 250.f, var = s2 / 250.f - mean * mean, rsg = rsqrtf(var + EPSF);
    float* o = core + (size_t)r * 250;
    for (int c = threadIdx.x; c < 250; c += 256) {
        float v = (row[c] - mean) * rsg;
        o[c] = v > 0.f ? v : 0.f;
    }
}

// ---------------- fused att ----------------
__global__ void k_att2(const float* __restrict__ part, const float* __restrict__ b1,
                       const float* __restrict__ w2, const float* __restrict__ b2,
                       float* __restrict__ att, int M, int nsplit) {
    __shared__ float row[128];
    int r = blockIdx.x;
    float s = 0.f, s2 = 0.f;
    for (int c = threadIdx.x; c < 100; c += 256) {
        float v = b1[c];
        for (int z = 0; z < nsplit; z++) v += part[((size_t)z * M + r) * 100 + c];
        row[c] = v; s += v; s2 += v * v;
    }
    reduce2(s, s2);
    float mean = s / 100.f, var = s2 / 100.f - mean * mean, rsg = rsqrtf(var + EPSF);
    float d = 0.f;
    for (int c = threadIdx.x; c < 100; c += 256)
        d += tanhf((row[c] - mean) * rsg) * w2[c];
    float dummy = 0.f;
    reduce2(d, dummy);
    if (threadIdx.x == 0) att[r] = 1.f / (1.f + expf(-(d + b2[0])));
}

// ---------------- fused effect + concat ----------------
__global__ void k_total2(const float* __restrict__ s1, const float* __restrict__ ctx,
                         const float* __restrict__ att, const float* __restrict__ hf,
                         float* __restrict__ total) {
    int idx = blockIdx.x * 256 + threadIdx.x;
    if (idx >= 384 * 1012) return;
    int n = idx / 1012, c = idx % 1012;
    float v;
    if (c < 250) v = s1[n * 250 + c];
    else if (c < 500) {
        int cc = c - 250;
        float s = 0.f;
        #pragma unroll
        for (int jj = 0; jj < 7; jj++)
            s += ctx[((size_t)n * 7 + jj) * 250 + cc] * att[n * 7 + jj];
        v = s;
    } else v = hf[n * 512 + (c - 500)];
    total[idx] = v;
}

// ---------------- fused state head ----------------
__global__ void k_state2(const float* __restrict__ part, const float* __restrict__ bias,
                         float* __restrict__ xr, float* __restrict__ so, int nsplit) {
    __shared__ float row[256];
    int r = blockIdx.x;
    float s = 0.f, s2 = 0.f;
    for (int c = threadIdx.x; c < 250; c += 256) {
        float v = bias[c];
        for (int z = 0; z < nsplit; z++) v += part[((size_t)z * 384 + r) * 250 + c];
        row[c] = v; s += v; s2 += v * v;
    }
    reduce2(s, s2);
    float mean = s / 250.f, var = s2 / 250.f - mean * mean, rsg = rsqrtf(var + EPSF);
    for (int c = threadIdx.x; c < 250; c += 256) {
        float v = row[c];
        xr[(size_t)r * 250 + c] = 1.f / (1.f + expf(-((v - mean) * rsg)));
        so[(size_t)r * 250 + c] = 1.f / (1.f + expf(-v));
    }
}

// ---------------- launch ----------------
extern "C" void kernel_launch(void* const* d_in, const int* in_sizes, int n_in,
                              void* d_out, int out_size) {
    const float* x     = (const float*)d_in[0];
    const float* state = (const float*)d_in[1];
    const float* c1w   = (const float*)d_in[2];  const float* c1b  = (const float*)d_in[3];
    const float* c2w   = (const float*)d_in[4];  const float* c2b  = (const float*)d_in[5];
    const float* c3w   = (const float*)d_in[6];  const float* c3b  = (const float*)d_in[7];
    const float* efcw  = (const float*)d_in[8];  const float* efcb = (const float*)d_in[9];
    const float* rencw = (const float*)d_in[10]; const float* rencb= (const float*)d_in[11];
    const float* corew = (const float*)d_in[12]; const float* coreb= (const float*)d_in[13];
    const float* ctxw  = (const float*)d_in[14]; const float* ctxb = (const float*)d_in[15];
    const float* att1w = (const float*)d_in[16]; const float* att1b= (const float*)d_in[17];
    const float* att2w = (const float*)d_in[18]; const float* att2b= (const float*)d_in[19];
    const float* outw  = (const float*)d_in[20]; const float* outb = (const float*)d_in[21];
    const float* dfc1w = (const float*)d_in[22]; const float* dfc1b= (const float*)d_in[23];
    const float* dfc2w = (const float*)d_in[24]; const float* dfc2b= (const float*)d_in[25];
    const float* d1w   = (const float*)d_in[26]; const float* d1b  = (const float*)d_in[27];
    const float* d2w   = (const float*)d_in[28]; const float* d2b  = (const float*)d_in[29];
    const float* d3w   = (const float*)d_in[30]; const float* d3b  = (const float*)d_in[31];
    float* out = (float*)d_out;

    float* S = nullptr;
    cudaGetSymbolAddress((void**)&S, g_scratch);
    float* h1   = S;                    // 6291456 (reused as dfc2 split scratch)
    float* h2   = h1  + 6291456;        // 3145728
    float* h3   = h2  + 3145728;        // 1572864
    float* hf   = h3  + 1572864;        // 196608
    float* s1   = hf  + 196608;         // 96000
    float* AB   = s1  + 96000;          // 192000
    float* core = AB  + 192000;         // 672000
    float* ctx  = core+ 672000;         // 672000
    float* att  = ctx + 672000;         // 2688
    float* tot  = att + 2688;           // 388608
    float* xr   = tot + 388608;         // 96000
    float* d1   = xr  + 96000;          // 196608
    float* d2   = d1  + 196608;         // 1572864
    float* dd1  = d2  + 1572864;        // 3145728
    float* dd2  = dd1 + 3145728;        // 6291456
    float* Bcat = dd2 + 6291456;        // 125000
    float* part = Bcat+ 125000;         // 1572864
    float* wgc1 = part+ 1572864;        // 256
    float* wgc2 = wgc1+ 256;            // 8192
    float* wgc3 = wgc2+ 8192;           // 32768
    float* wgd1 = wgc3+ 32768;          // 32768
    float* wgd2 = wgd1+ 32768;          // 8192
    float* wgd3 = wgd2+ 8192;           // 256

    const float* NOB = nullptr;

    // ---- merged weight repack + Bcat (one launch) ----
    k_repack_all<<<512, 256>>>(c1w, c2w, c3w, d1w, d2w, d3w, corew,
                               wgc1, wgc2, wgc3, wgd1, wgd2, wgd3, Bcat);

    // ---- encoder (implicit-GEMM tf32 convs + LN passes) ----
    k_conv_mma<64,1,16,2,0><<<1536, 256>>>(x, wgc1, c1b, h1);
    k_ln_act<<<384, 256>>>(h1, 16384, 0);
    k_conv_mma<32,16,32,2,0><<<384, 256>>>(h1, wgc2, c2b, h2);
    k_ln_act<<<384, 256>>>(h2, 8192, 0);
    k_conv_mma<16,32,64,1,0><<<192, 256>>>(h2, wgc3, c3b, h3);
    k_ln_act<<<384, 256>>>(h3, 4096, 0);
    { dim3 g(8, 6, 8); k_gemm_tc<<<g, 256>>>(h3, efcw, NOB, part, 384, 512, 4096, 32); }
    k_reduce_ln<<<384, 256>>>(part, efcb, hf, 384, 512, 8, 0);

    // ---- recurrent / pairwise ----
    { dim3 g(4, 6, 8); k_gemm_tc<<<g, 256>>>(state, rencw, NOB, part, 384, 250, 250, 2); }
    k_reduce_ln<<<384, 256>>>(part, rencb, s1, 384, 250, 8, 1);
    { dim3 g(8, 6, 4); k_gemm_tc<<<g, 256>>>(s1, Bcat, NOB, part, 384, 500, 250, 4); }
    k_reduce_ln<<<384, 256>>>(part, NOB, AB, 384, 500, 4, -1);
    k_core<<<2688, 256>>>(AB, coreb, core);
    { dim3 g(4, 42, 2); k_gemm_tc<<<g, 256>>>(core, ctxw, NOB, part, 2688, 250, 250, 8); }
    k_reduce_ln<<<2688, 256>>>(part, ctxb, ctx, 2688, 250, 2, 1);
    { dim3 g(2, 42, 4); k_gemm_tc<<<g, 256>>>(core, att1w, NOB, part, 2688, 100, 250, 4); }
    k_att2<<<2688, 256>>>(part, att1b, att2w, att2b, att, 2688, 4);
    k_total2<<<(388608 + 255) / 256, 256>>>(s1, ctx, att, hf, tot);
    { dim3 g(4, 6, 8); k_gemm_tc<<<g, 256>>>(tot, outw, NOB, part, 384, 250, 1012, 8); }
    k_state2<<<384, 256>>>(part, outb, xr, out + 384 * 4096, 8);

    // ---- decoder ----
    { dim3 g(8, 6, 4); k_gemm_tc<<<g, 256>>>(xr, dfc1w, NOB, part, 384, 512, 250, 4); }
    k_reduce_ln<<<384, 256>>>(part, dfc1b, d1, 384, 512, 4, 1);
    { dim3 g(64, 6, 2); k_gemm_tc<<<g, 256>>>(d1, dfc2w, NOB, h1, 384, 4096, 512, 16); }
    k_reduce_ln<<<384, 256>>>(h1, dfc2b, d2, 384, 4096, 2, 1);
    k_deconv_mma<8,64,32,1,0><<<dim3(192, 4), 256>>>(d2, wgd1, d1b, dd1);
    k_ln_act<<<384, 256>>>(dd1, 8192, 1);
    k_deconv_mma<16,32,16,2,0><<<dim3(384, 4), 256>>>(dd1, wgd2, d2b, dd2);
    k_ln_act<<<384, 256>>>(dd2, 16384, 1);
    k_deconv_mma<32,16,1,2,2><<<dim3(1536, 4), 256>>>(dd2, wgd3, d3b, out);
}

// round 17
// speedup vs baseline: 1.2325x; 1.0171x over previous
#include <cuda_runtime.h>
#include <math.h>

#define EPSF 1e-5f

// ---------------- scratch arena ----------------
__device__ float g_scratch[28649672];

__host__ __device__ constexpr int clog2(int x) { int r = 0; while ((1 << r) < x) r++; return r; }

// ---------------- block reduction (blockDim.x == 256) ----------------
__device__ __forceinline__ void reduce2(float& s, float& s2) {
    __shared__ float rA[256];
    __shared__ float rB[256];
    __syncthreads();
    int t = threadIdx.x;
    rA[t] = s; rB[t] = s2;
    __syncthreads();
    for (int off = 128; off > 0; off >>= 1) {
        if (t < off) { rA[t] += rA[t + off]; rB[t] += rB[t + off]; }
        __syncthreads();
    }
    s = rA[0]; s2 = rB[0];
}

// ---------------- tf32 helpers ----------------
__device__ __forceinline__ unsigned int f2tf32(float f) {
    unsigned int u;
    asm("cvt.rna.tf32.f32 %0, %1;" : "=r"(u) : "f"(f));
    return u;
}

__device__ __forceinline__ void mma_tf32(float c[4], const unsigned int a[4],
                                         unsigned int b0, unsigned int b1) {
    asm volatile(
        "mma.sync.aligned.m16n8k8.row.col.f32.tf32.tf32.f32 "
        "{%0,%1,%2,%3}, {%4,%5,%6,%7}, {%8,%9}, {%0,%1,%2,%3};\n"
        : "+f"(c[0]), "+f"(c[1]), "+f"(c[2]), "+f"(c[3])
        : "r"(a[0]), "r"(a[1]), "r"(a[2]), "r"(a[3]), "r"(b0), "r"(b1));
}

// ---------------- merged weight repack + Bcat (one launch, grid 512) ----------------
template<int C_IN, int C_OUT>
__device__ __forceinline__ void repack_enc(int idx, const float* __restrict__ w,
                                           float* __restrict__ Wg) {
    if (idx >= 16 * C_IN * C_OUT) return;
    int o = idx % C_OUT; int rem = idx / C_OUT;
    int c = rem % C_IN;  int tap = rem / C_IN;
    int kh = tap & 3, kw = tap >> 2;
    Wg[idx] = w[((o * C_IN + c) * 4 + kh) * 4 + kw];
}

template<int C_IN, int C_OUT>
__device__ __forceinline__ void repack_dec(int idx, const float* __restrict__ w,
                                           float* __restrict__ Wg) {
    if (idx >= 16 * C_IN * C_OUT) return;
    int o = idx % C_OUT; int rem = idx / C_OUT;
    int c = rem % C_IN;  int rem2 = rem / C_IN;
    int g = rem2 & 3;    int pp = rem2 >> 2;
    int pa = pp >> 1, pb = pp & 1, ga = g >> 1, gb = g & 1;
    int kw0, kw1, kh0, kh1;
    if (pa == 0) { if (ga == 0) { kw0 = 0; kw1 = 1; } else { kw0 = 1; kw1 = 4; } }
    else         { if (ga == 0) { kw0 = 0; kw1 = 3; } else { kw0 = 3; kw1 = 4; } }
    if (pb == 0) { if (gb == 0) { kh0 = 0; kh1 = 1; } else { kh0 = 1; kh1 = 4; } }
    else         { if (gb == 0) { kh0 = 0; kh1 = 3; } else { kh0 = 3; kh1 = 4; } }
    float sum = 0.f;
    for (int kw = kw0; kw < kw1; kw++)
        for (int kh = kh0; kh < kh1; kh++)
            sum += w[(((size_t)o * C_IN + c) * 4 + kh) * 4 + kw];
    Wg[idx] = sum;
}

__global__ void k_repack_all(const float* __restrict__ c1w, const float* __restrict__ c2w,
                             const float* __restrict__ c3w, const float* __restrict__ d1w,
                             const float* __restrict__ d2w, const float* __restrict__ d3w,
                             const float* __restrict__ corew,
                             float* wgc1, float* wgc2, float* wgc3,
                             float* wgd1, float* wgd2, float* wgd3,
                             float* Bcat) {
    int idx = blockIdx.x * 256 + threadIdx.x;
    repack_enc<1, 16>(idx, c1w, wgc1);
    repack_enc<16, 32>(idx, c2w, wgc2);
    repack_enc<32, 64>(idx, c3w, wgc3);
    repack_dec<64, 32>(idx, d1w, wgd1);
    repack_dec<32, 16>(idx, d2w, wgd2);
    repack_dec<16, 1>(idx, d3w, wgd3);
    if (idx < 250 * 500) {
        int k = idx / 500, n = idx % 500;
        Bcat[idx] = (n < 250) ? corew[k * 250 + n] : corew[(k + 250) * 250 + (n - 250)];
    }
}

// ---------------- implicit-GEMM tf32 encoder conv (stride2, pad1, k4) ----------------
// MT m-subtiles per warp (CTA covers 128*MT pixels). Conflict-free smem strides.
template<int S_IN, int C_IN, int C_OUT, int MT, int ACT>
__global__ void __launch_bounds__(256)
k_conv_mma(const float* __restrict__ in, const float* __restrict__ Wg,
           const float* __restrict__ bias, float* __restrict__ out) {
    constexpr int S_OUT = S_IN / 2;
    constexpr int PS    = S_OUT * S_OUT;
    constexpr int PIX   = 128 * MT;
    constexpr int K_TOT = 16 * C_IN;
    constexpr int KC    = (K_TOT >= 32) ? 32 : K_TOT;
    constexpr int TPP   = 256 / PIX;
    constexpr int KEL   = KC / TPP;
    constexpr int NB    = (C_OUT < 8) ? 8 : C_OUT;
    constexpr int NT    = NB / 8;
    constexpr int AS    = PIX + 8;
    constexpr int BSs   = (NB % 32 == 0) ? NB + 8 : 40;
    constexpr int LC = clog2(C_IN), LPS = clog2(PS), LSO = clog2(S_OUT);
    __shared__ float As[KC][AS];
    __shared__ float Bs[KC][BSs];
    int tid = threadIdx.x;
    int warp = tid >> 5, lane = tid & 31, gid = lane >> 2, tig = lane & 3;
    int p_loc = tid % PIX;
    int koff  = (tid / PIX) * KEL;
    int m0 = blockIdx.x * PIX;
    int p_glob = m0 + p_loc;
    int n = p_glob >> LPS;
    int l = p_glob & (PS - 1);
    int a = l >> LSO, b = l & (S_OUT - 1);
    const float* inb = in + (size_t)n * S_IN * S_IN * C_IN;
    float acc[MT][NT][4];
    #pragma unroll
    for (int mt = 0; mt < MT; mt++)
        #pragma unroll
        for (int i = 0; i < NT; i++)
            { acc[mt][i][0] = acc[mt][i][1] = acc[mt][i][2] = acc[mt][i][3] = 0.f; }

    for (int k0 = 0; k0 < K_TOT; k0 += KC) {
        // A staging (implicit im2col)
        if constexpr (C_IN >= 4) {
            #pragma unroll
            for (int j = 0; j < KEL; j += 4) {
                int k = k0 + koff + j;
                int tap = k >> LC;
                int c0  = k & (C_IN - 1);
                int u = 2 * a - 1 + (tap >> 2);
                int v = 2 * b - 1 + (tap & 3);
                bool ok = (u >= 0) && (u < S_IN) && (v >= 0) && (v < S_IN);
                float4 xv = ok ? *reinterpret_cast<const float4*>(
                                    inb + ((size_t)u * S_IN + v) * C_IN + c0)
                               : make_float4(0.f, 0.f, 0.f, 0.f);
                As[koff + j + 0][p_loc] = xv.x; As[koff + j + 1][p_loc] = xv.y;
                As[koff + j + 2][p_loc] = xv.z; As[koff + j + 3][p_loc] = xv.w;
            }
        } else {
            #pragma unroll
            for (int j = 0; j < KEL; j++) {
                int k = k0 + koff + j;
                int tap = k >> LC;
                int c = k & (C_IN - 1);
                int u = 2 * a - 1 + (tap >> 2);
                int v = 2 * b - 1 + (tap & 3);
                bool ok = (u >= 0) && (u < S_IN) && (v >= 0) && (v < S_IN);
                As[koff + j][p_loc] = ok ? inb[((size_t)u * S_IN + v) * C_IN + c] : 0.f;
            }
        }
        // B staging
        for (int idx = tid; idx < KC * NB; idx += 256) {
            int kk = idx / NB, o = idx % NB;
            Bs[kk][o] = (o < C_OUT) ? Wg[(size_t)(k0 + kk) * C_OUT + o] : 0.f;
        }
        __syncthreads();
        #pragma unroll
        for (int ks = 0; ks < KC; ks += 8) {
            unsigned int bf[NT][2];
            #pragma unroll
            for (int nt = 0; nt < NT; nt++) {
                bf[nt][0] = f2tf32(Bs[ks + tig][nt * 8 + gid]);
                bf[nt][1] = f2tf32(Bs[ks + tig + 4][nt * 8 + gid]);
            }
            #pragma unroll
            for (int mt = 0; mt < MT; mt++) {
                unsigned int af[4];
                int mb = warp * 16 * MT + mt * 16 + gid;
                af[0] = f2tf32(As[ks + tig][mb]);
                af[1] = f2tf32(As[ks + tig][mb + 8]);
                af[2] = f2tf32(As[ks + tig + 4][mb]);
                af[3] = f2tf32(As[ks + tig + 4][mb + 8]);
                #pragma unroll
                for (int nt = 0; nt < NT; nt++)
                    mma_tf32(acc[mt][nt], af, bf[nt][0], bf[nt][1]);
            }
        }
        __syncthreads();
    }
    #pragma unroll
    for (int mt = 0; mt < MT; mt++) {
        int pixA = m0 + warp * 16 * MT + mt * 16 + gid;
        int pixB = pixA + 8;
        float* oA = out + (size_t)pixA * C_OUT;
        float* oB = out + (size_t)pixB * C_OUT;
        #pragma unroll
        for (int nt = 0; nt < NT; nt++) {
            int o = nt * 8 + tig * 2;
            if (o < C_OUT) {
                oA[o]     = acc[mt][nt][0] + bias[o];
                oA[o + 1] = acc[mt][nt][1] + bias[o + 1];
                oB[o]     = acc[mt][nt][2] + bias[o];
                oB[o + 1] = acc[mt][nt][3] + bias[o + 1];
            }
        }
    }
}

// ---------------- implicit-GEMM tf32 decoder deconv (up4+conv, 4x FLOP-reduced) ----------------
// One output-parity plane per blockIdx.y. MT m-subtiles per warp. ACT: 0 raw, 2 sigmoid.
template<int S_IN, int C_IN, int C_OUT, int MT, int ACT>
__global__ void __launch_bounds__(256)
k_deconv_mma(const float* __restrict__ in, const float* __restrict__ Wg,
             const float* __restrict__ bias, float* __restrict__ out) {
    constexpr int S_OUT = 2 * S_IN;
    constexpr int PS    = S_IN * S_IN;
    constexpr int PIX   = 128 * MT;
    constexpr int K_TOT = 4 * C_IN;
    constexpr int KC    = (K_TOT >= 32) ? 32 : K_TOT;
    constexpr int TPP   = 256 / PIX;
    constexpr int KEL   = KC / TPP;
    constexpr int NB    = (C_OUT < 8) ? 8 : C_OUT;
    constexpr int NT    = NB / 8;
    constexpr int AS    = PIX + 8;
    constexpr int BSs   = (NB % 32 == 0) ? NB + 8 : 40;
    constexpr int LC = clog2(C_IN), LPS = clog2(PS), LSI = clog2(S_IN);
    __shared__ float As[KC][AS];
    __shared__ float Bs[KC][BSs];
    int tid = threadIdx.x;
    int warp = tid >> 5, lane = tid & 31, gid = lane >> 2, tig = lane & 3;
    int pp = blockIdx.y;
    int pa = pp >> 1, pb = pp & 1;
    const float* Wp = Wg + (size_t)pp * 4 * C_IN * C_OUT;
    int p_loc = tid % PIX;
    int koff  = (tid / PIX) * KEL;
    int m0 = blockIdx.x * PIX;
    int p_glob = m0 + p_loc;
    int n = p_glob >> LPS;
    int l = p_glob & (PS - 1);
    int ma = l >> LSI, mb2 = l & (S_IN - 1);
    const float* inb = in + (size_t)n * S_IN * S_IN * C_IN;
    float acc[MT][NT][4];
    #pragma unroll
    for (int mt = 0; mt < MT; mt++)
        #pragma unroll
        for (int i = 0; i < NT; i++)
            { acc[mt][i][0] = acc[mt][i][1] = acc[mt][i][2] = acc[mt][i][3] = 0.f; }

    for (int k0 = 0; k0 < K_TOT; k0 += KC) {
        #pragma unroll
        for (int j = 0; j < KEL; j += 4) {
            int k = k0 + koff + j;
            int g  = k >> LC;
            int c0 = k & (C_IN - 1);
            int su = (g & 2) ? (pa ? ma + 1 : ma) : (pa ? ma : ma - 1);
            int sv = (g & 1) ? (pb ? mb2 + 1 : mb2) : (pb ? mb2 : mb2 - 1);
            bool ok = (su >= 0) && (su < S_IN) && (sv >= 0) && (sv < S_IN);
            float4 xv = ok ? *reinterpret_cast<const float4*>(
                                inb + ((size_t)su * S_IN + sv) * C_IN + c0)
                           : make_float4(0.f, 0.f, 0.f, 0.f);
            As[koff + j + 0][p_loc] = xv.x; As[koff + j + 1][p_loc] = xv.y;
            As[koff + j + 2][p_loc] = xv.z; As[koff + j + 3][p_loc] = xv.w;
        }
        for (int idx = tid; idx < KC * NB; idx += 256) {
            int kk = idx / NB, o = idx % NB;
            Bs[kk][o] = (o < C_OUT) ? Wp[(size_t)(k0 + kk) * C_OUT + o] : 0.f;
        }
        __syncthreads();
        #pragma unroll
        for (int ks = 0; ks < KC; ks += 8) {
            unsigned int bf[NT][2];
            #pragma unroll
            for (int nt = 0; nt < NT; nt++) {
                bf[nt][0] = f2tf32(Bs[ks + tig][nt * 8 + gid]);
                bf[nt][1] = f2tf32(Bs[ks + tig + 4][nt * 8 + gid]);
            }
            #pragma unroll
            for (int mt = 0; mt < MT; mt++) {
                unsigned int af[4];
                int mrow = warp * 16 * MT + mt * 16 + gid;
                af[0] = f2tf32(As[ks + tig][mrow]);
                af[1] = f2tf32(As[ks + tig][mrow + 8]);
                af[2] = f2tf32(As[ks + tig + 4][mrow]);
                af[3] = f2tf32(As[ks + tig + 4][mrow + 8]);
                #pragma unroll
                for (int nt = 0; nt < NT; nt++)
                    mma_tf32(acc[mt][nt], af, bf[nt][0], bf[nt][1]);
            }
        }
        __syncthreads();
    }
    #pragma unroll
    for (int mt = 0; mt < MT; mt++) {
        #pragma unroll
        for (int half = 0; half < 2; half++) {
            int pix = m0 + warp * 16 * MT + mt * 16 + gid + half * 8;
            int nE = pix >> LPS;
            int lE = pix & (PS - 1);
            int aE = 2 * (lE >> LSI) + pa;
            int bE = 2 * (lE & (S_IN - 1)) + pb;
            float* op = out + (((size_t)nE * S_OUT + aE) * S_OUT + bE) * C_OUT;
            if constexpr (C_OUT == 1) {
                if (tig == 0) {
                    float v = acc[mt][0][half * 2] + bias[0];
                    op[0] = (ACT == 2) ? (1.f / (1.f + expf(-v))) : v;
                }
            } else {
                #pragma unroll
                for (int nt = 0; nt < NT; nt++) {
                    int o = nt * 8 + tig * 2;
                    op[o]     = acc[mt][nt][half * 2 + 0] + bias[o];
                    op[o + 1] = acc[mt][nt][half * 2 + 1] + bias[o + 1];
                }
            }
        }
    }
}

// ---------------- tf32 tensor-core split-K GEMM (64x64 tile, mma.m16n8k8) ----------------
__global__ void k_gemm_tc(const float* __restrict__ A, const float* __restrict__ B,
                          const float* __restrict__ bias, float* __restrict__ C,
                          int M, int N, int K, int ksteps_split) {
    __shared__ float As[16][72];
    __shared__ float Bs[16][72];
    int tid = threadIdx.x;
    int warp = tid >> 5, lane = tid & 31;
    int gid = lane >> 2, tig = lane & 3;
    int wm = warp >> 1, wn = warp & 1;
    int n0 = blockIdx.x * 64, m0 = blockIdx.y * 64;
    int k_begin = blockIdx.z * ksteps_split * 16;
    int k_end = min(K, k_begin + ksteps_split * 16);
    float c[4][4] = {};
    for (int k0 = k_begin; k0 < k_end; k0 += 16) {
        #pragma unroll
        for (int r = 0; r < 4; r++) {
            int idx = tid + r * 256;
            int mm = idx >> 4, kk = idx & 15;
            int gm = m0 + mm, gk = k0 + kk;
            As[kk][mm] = (gm < M && gk < K) ? A[(size_t)gm * K + gk] : 0.f;
            int kk2 = idx >> 6, nn = idx & 63;
            int gk2 = k0 + kk2, gn = n0 + nn;
            Bs[kk2][nn] = (gk2 < K && gn < N) ? B[(size_t)gk2 * N + gn] : 0.f;
        }
        __syncthreads();
        #pragma unroll
        for (int ks = 0; ks < 16; ks += 8) {
            unsigned int a[4];
            int mb = wm * 16 + gid;
            a[0] = f2tf32(As[ks + tig][mb]);
            a[1] = f2tf32(As[ks + tig][mb + 8]);
            a[2] = f2tf32(As[ks + tig + 4][mb]);
            a[3] = f2tf32(As[ks + tig + 4][mb + 8]);
            #pragma unroll
            for (int nt = 0; nt < 4; nt++) {
                int nb = wn * 32 + nt * 8 + gid;
                unsigned int b0 = f2tf32(Bs[ks + tig][nb]);
                unsigned int b1 = f2tf32(Bs[ks + tig + 4][nb]);
                mma_tf32(c[nt], a, b0, b1);
            }
        }
        __syncthreads();
    }
    float* Cw = C + (size_t)blockIdx.z * M * N;
    int mA = m0 + wm * 16 + gid;
    int mB = mA + 8;
    #pragma unroll
    for (int nt = 0; nt < 4; nt++) {
        int n = n0 + wn * 32 + nt * 8 + tig * 2;
        if (n < N) {
            float bb0 = bias ? bias[n] : 0.f;
            float bb1 = (n + 1 < N && bias) ? bias[n + 1] : 0.f;
            if (mA < M) {
                Cw[(size_t)mA * N + n] = c[nt][0] + bb0;
                if (n + 1 < N) Cw[(size_t)mA * N + n + 1] = c[nt][1] + bb1;
            }
            if (mB < M) {
                Cw[(size_t)mB * N + n] = c[nt][2] + bb0;
                if (n + 1 < N) Cw[(size_t)mB * N + n + 1] = c[nt][3] + bb1;
            }
        }
    }
}

// ---------------- split-K reduce + bias + optional row-LN + act ----------------
// float4 fast path when N % 4 == 0.
__global__ void k_reduce_ln(const float* __restrict__ part, const float* __restrict__ bias,
                            float* __restrict__ out, int M, int N, int nsplit, int act) {
    int r = blockIdx.x;
    float s = 0.f, s2 = 0.f;
    if ((N & 3) == 0) {
        int n4 = N >> 2;
        float4* o4 = reinterpret_cast<float4*>(out + (size_t)r * N);
        for (int c = threadIdx.x; c < n4; c += 256) {
            float4 v = bias ? reinterpret_cast<const float4*>(bias)[c]
                            : make_float4(0.f, 0.f, 0.f, 0.f);
            for (int z = 0; z < nsplit; z++) {
                float4 p = reinterpret_cast<const float4*>(
                    part + ((size_t)z * M + r) * N)[c];
                v.x += p.x; v.y += p.y; v.z += p.z; v.w += p.w;
            }
            o4[c] = v;
            s  += v.x + v.y + v.z + v.w;
            s2 += v.x * v.x + v.y * v.y + v.z * v.z + v.w * v.w;
        }
        if (act < 0) return;
        reduce2(s, s2);
        float mean = s / N, var = s2 / N - mean * mean, rsg = rsqrtf(var + EPSF);
        for (int c = threadIdx.x; c < n4; c += 256) {
            float4 v = o4[c];
            float a0 = (v.x - mean) * rsg, a1 = (v.y - mean) * rsg;
            float a2 = (v.z - mean) * rsg, a3 = (v.w - mean) * rsg;
            if (act == 0) {
                v.x = a0 > 0.f ? a0 : expm1f(a0); v.y = a1 > 0.f ? a1 : expm1f(a1);
                v.z = a2 > 0.f ? a2 : expm1f(a2); v.w = a3 > 0.f ? a3 : expm1f(a3);
            } else {
                v.x = a0 > 0.f ? a0 : 0.f; v.y = a1 > 0.f ? a1 : 0.f;
                v.z = a2 > 0.f ? a2 : 0.f; v.w = a3 > 0.f ? a3 : 0.f;
            }
            o4[c] = v;
        }
        return;
    }
    for (int c = threadIdx.x; c < N; c += 256) {
        float v = bias ? bias[c] : 0.f;
        for (int z = 0; z < nsplit; z++) v += part[((size_t)z * M + r) * N + c];
        out[(size_t)r * N + c] = v;
        s += v; s2 += v * v;
    }
    if (act < 0) return;
    reduce2(s, s2);
    float mean = s / N, var = s2 / N - mean * mean, rsg = rsqrtf(var + EPSF);
    for (int c = threadIdx.x; c < N; c += 256) {
        float v = (out[(size_t)r * N + c] - mean) * rsg;
        out[(size_t)r * N + c] = (act == 0) ? (v > 0.f ? v : expm1f(v)) : (v > 0.f ? v : 0.f);
    }
}

// ---------------- per-row layernorm + act, in-place, float4 (N % 4 == 0) ----------------
__global__ void k_ln_act(float* __restrict__ X, int N, int act) {
    int r = blockIdx.x;
    float4* x = reinterpret_cast<float4*>(X + (size_t)r * N);
    int n4 = N >> 2;
    float s = 0.f, s2 = 0.f;
    for (int c = threadIdx.x; c < n4; c += 256) {
        float4 v = x[c];
        s  += v.x + v.y + v.z + v.w;
        s2 += v.x * v.x + v.y * v.y + v.z * v.z + v.w * v.w;
    }
    reduce2(s, s2);
    float mean = s / N, var = s2 / N - mean * mean, rsg = rsqrtf(var + EPSF);
    for (int c = threadIdx.x; c < n4; c += 256) {
        float4 v = x[c];
        float a0 = (v.x - mean) * rsg, a1 = (v.y - mean) * rsg;
        float a2 = (v.z - mean) * rsg, a3 = (v.w - mean) * rsg;
        if (act == 0) {
            v.x = a0 > 0.f ? a0 : expm1f(a0); v.y = a1 > 0.f ? a1 : expm1f(a1);
            v.z = a2 > 0.f ? a2 : expm1f(a2); v.w = a3 > 0.f ? a3 : expm1f(a3);
        } else {
            v.x = a0 > 0.f ? a0 : 0.f; v.y = a1 > 0.f ? a1 : 0.f;
            v.z = a2 > 0.f ? a2 : 0.f; v.w = a3 > 0.f ? a3 : 0.f;
        }
        x[c] = v;
    }
}

// ---------------- core rows ----------------
__global__ void k_core(const float* __restrict__ AB, const float* __restrict__ bias,
                       float* __restrict__ core) {
    int r = blockIdx.x;
    int jj = r % 7; int fi = r / 7; int i = fi % 8; int bi = fi / 8;
    int j = (jj < i) ? jj : jj + 1;
    const float* ar = AB + (size_t)fi * 500;
    const float* br = AB + (size_t)(bi * 8 + j) * 500 + 250;
    __shared__ float row[256];
    float s = 0.f, s2 = 0.f;
    for (int c = threadIdx.x; c < 250; c += 256) {
        float v = ar[c] + br[c] + bias[c];
        row[c] = v; s += v; s2 += v * v;
    }
    reduce2(s, s2);
    float mean = s / 250.f, var = s2 / 250.f - mean * mean, rsg = rsqrtf(var + EPSF);
    float* o = core + (size_t)r * 250;
    for (int c = threadIdx.x; c < 250; c += 256) {
        float v = (row[c] - mean) * rsg;
        o[c] = v > 0.f ? v : 0.f;
    }
}

// ---------------- fused: ctx reduce+LN+ReLU AND att reduce+LN+tanh-dot+sigmoid ----------------
// partA: [nsA][2688][250] ctx partials; partB: [nsB][2688][100] att1 partials.
__global__ void k_ctx_att(const float* __restrict__ partA, const float* __restrict__ ctxb,
                          const float* __restrict__ partB, const float* __restrict__ b1,
                          const float* __restrict__ w2, const float* __restrict__ b2,
                          float* __restrict__ ctx, float* __restrict__ att,
                          int nsA, int nsB) {
    int r = blockIdx.x;                         // M = 2688
    __shared__ float rowB[128];
    // --- ctx part ---
    float s = 0.f, s2 = 0.f;
    float* oc = ctx + (size_t)r * 250;
    for (int c = threadIdx.x; c < 250; c += 256) {
        float v = ctxb[c];
        for (int z = 0; z < nsA; z++) v += partA[((size_t)z * 2688 + r) * 250 + c];
        oc[c] = v;
        s += v; s2 += v * v;
    }
    reduce2(s, s2);
    {
        float mean = s / 250.f, var = s2 / 250.f - mean * mean, rsg = rsqrtf(var + EPSF);
        for (int c = threadIdx.x; c < 250; c += 256) {
            float v = (oc[c] - mean) * rsg;
            oc[c] = v > 0.f ? v : 0.f;
        }
    }
    // --- att part ---
    float sa = 0.f, sa2 = 0.f;
    for (int c = threadIdx.x; c < 100; c += 256) {
        float v = b1[c];
        for (int z = 0; z < nsB; z++) v += partB[((size_t)z * 2688 + r) * 100 + c];
        rowB[c] = v; sa += v; sa2 += v * v;
    }
    reduce2(sa, sa2);
    float meanA = sa / 100.f, varA = sa2 / 100.f - meanA * meanA, rsgA = rsqrtf(varA + EPSF);
    float d = 0.f;
    for (int c = threadIdx.x; c < 100; c += 256)
        d += tanhf((rowB[c] - meanA) * rsgA) * w2[c];
    float dummy = 0.f;
    reduce2(d, dummy);
    if (threadIdx.x == 0) att[r] = 1.f / (1.f + expf(-(d + b2[0])));
}

// ---------------- fused effect + concat ----------------
__global__ void k_total2(const float* __restrict__ s1, const float* __restrict__ ctx,
                         const float* __restrict__ att, const float* __restrict__ hf,
                         float* __restrict__ total) {
    int idx = blockIdx.x * 256 + threadIdx.x;
    if (idx >= 384 * 1012) return;
    int n = idx / 1012, c = idx % 1012;
    float v;
    if (c < 250) v = s1[n * 250 + c];
    else if (c < 500) {
        int cc = c - 250;
        float s = 0.f;
        #pragma unroll
        for (int jj = 0; jj < 7; jj++)
            s += ctx[((size_t)n * 7 + jj) * 250 + cc] * att[n * 7 + jj];
        v = s;
    } else v = hf[n * 512 + (c - 500)];
    total[idx] = v;
}

// ---------------- fused state head ----------------
__global__ void k_state2(const float* __restrict__ part, const float* __restrict__ bias,
                         float* __restrict__ xr, float* __restrict__ so, int nsplit) {
    __shared__ float row[256];
    int r = blockIdx.x;
    float s = 0.f, s2 = 0.f;
    for (int c = threadIdx.x; c < 250; c += 256) {
        float v = bias[c];
        for (int z = 0; z < nsplit; z++) v += part[((size_t)z * 384 + r) * 250 + c];
        row[c] = v; s += v; s2 += v * v;
    }
    reduce2(s, s2);
    float mean = s / 250.f, var = s2 / 250.f - mean * mean, rsg = rsqrtf(var + EPSF);
    for (int c = threadIdx.x; c < 250; c += 256) {
        float v = row[c];
        xr[(size_t)r * 250 + c] = 1.f / (1.f + expf(-((v - mean) * rsg)));
        so[(size_t)r * 250 + c] = 1.f / (1.f + expf(-v));
    }
}

// ---------------- launch ----------------
extern "C" void kernel_launch(void* const* d_in, const int* in_sizes, int n_in,
                              void* d_out, int out_size) {
    const float* x     = (const float*)d_in[0];
    const float* state = (const float*)d_in[1];
    const float* c1w   = (const float*)d_in[2];  const float* c1b  = (const float*)d_in[3];
    const float* c2w   = (const float*)d_in[4];  const float* c2b  = (const float*)d_in[5];
    const float* c3w   = (const float*)d_in[6];  const float* c3b  = (const float*)d_in[7];
    const float* efcw  = (const float*)d_in[8];  const float* efcb = (const float*)d_in[9];
    const float* rencw = (const float*)d_in[10]; const float* rencb= (const float*)d_in[11];
    const float* corew = (const float*)d_in[12]; const float* coreb= (const float*)d_in[13];
    const float* ctxw  = (const float*)d_in[14]; const float* ctxb = (const float*)d_in[15];
    const float* att1w = (const float*)d_in[16]; const float* att1b= (const float*)d_in[17];
    const float* att2w = (const float*)d_in[18]; const float* att2b= (const float*)d_in[19];
    const float* outw  = (const float*)d_in[20]; const float* outb = (const float*)d_in[21];
    const float* dfc1w = (const float*)d_in[22]; const float* dfc1b= (const float*)d_in[23];
    const float* dfc2w = (const float*)d_in[24]; const float* dfc2b= (const float*)d_in[25];
    const float* d1w   = (const float*)d_in[26]; const float* d1b  = (const float*)d_in[27];
    const float* d2w   = (const float*)d_in[28]; const float* d2b  = (const float*)d_in[29];
    const float* d3w   = (const float*)d_in[30]; const float* d3b  = (const float*)d_in[31];
    float* out = (float*)d_out;

    float* S = nullptr;
    cudaGetSymbolAddress((void**)&S, g_scratch);
    float* h1   = S;                    // 6291456 (reused as dfc2 split scratch)
    float* h2   = h1  + 6291456;        // 3145728
    float* h3   = h2  + 3145728;        // 1572864
    float* hf   = h3  + 1572864;        // 196608
    float* s1   = hf  + 196608;         // 96000
    float* AB   = s1  + 96000;          // 192000
    float* core = AB  + 192000;         // 672000
    float* ctx  = core+ 672000;         // 672000
    float* att  = ctx + 672000;         // 2688
    float* tot  = att + 2688;           // 388608
    float* xr   = tot + 388608;         // 96000
    float* d1   = xr  + 96000;          // 196608
    float* d2   = d1  + 196608;         // 1572864
    float* dd1  = d2  + 1572864;        // 3145728
    float* dd2  = dd1 + 3145728;        // 6291456
    float* Bcat = dd2 + 6291456;        // 125000
    float* part = Bcat+ 125000;         // 1572864
    float* wgc1 = part+ 1572864;        // 256
    float* wgc2 = wgc1+ 256;            // 8192
    float* wgc3 = wgc2+ 8192;           // 32768
    float* wgd1 = wgc3+ 32768;          // 32768
    float* wgd2 = wgd1+ 32768;          // 8192
    float* wgd3 = wgd2+ 8192;           // 256
    float* partB= wgd3+ 256;            // 1075200 (att1 partials)

    const float* NOB = nullptr;

    // ---- merged weight repack + Bcat (one launch) ----
    k_repack_all<<<512, 256>>>(c1w, c2w, c3w, d1w, d2w, d3w, corew,
                               wgc1, wgc2, wgc3, wgd1, wgd2, wgd3, Bcat);

    // ---- encoder (implicit-GEMM tf32 convs + LN passes) ----
    k_conv_mma<64,1,16,2,0><<<1536, 256>>>(x, wgc1, c1b, h1);
    k_ln_act<<<384, 256>>>(h1, 16384, 0);
    k_conv_mma<32,16,32,2,0><<<384, 256>>>(h1, wgc2, c2b, h2);
    k_ln_act<<<384, 256>>>(h2, 8192, 0);
    k_conv_mma<16,32,64,1,0><<<192, 256>>>(h2, wgc3, c3b, h3);
    k_ln_act<<<384, 256>>>(h3, 4096, 0);
    { dim3 g(8, 6, 8); k_gemm_tc<<<g, 256>>>(h3, efcw, NOB, part, 384, 512, 4096, 32); }
    k_reduce_ln<<<384, 256>>>(part, efcb, hf, 384, 512, 8, 0);

    // ---- recurrent / pairwise ----
    { dim3 g(4, 6, 8); k_gemm_tc<<<g, 256>>>(state, rencw, NOB, part, 384, 250, 250, 2); }
    k_reduce_ln<<<384, 256>>>(part, rencb, s1, 384, 250, 8, 1);
    { dim3 g(8, 6, 4); k_gemm_tc<<<g, 256>>>(s1, Bcat, NOB, part, 384, 500, 250, 4); }
    k_reduce_ln<<<384, 256>>>(part, NOB, AB, 384, 500, 4, -1);
    k_core<<<2688, 256>>>(AB, coreb, core);
    { dim3 g(2, 42, 4); k_gemm_tc<<<g, 256>>>(core, att1w, NOB, partB, 2688, 100, 250, 4); }
    { dim3 g(4, 42, 2); k_gemm_tc<<<g, 256>>>(core, ctxw, NOB, part, 2688, 250, 250, 8); }
    k_ctx_att<<<2688, 256>>>(part, ctxb, partB, att1b, att2w, att2b, ctx, att, 2, 4);
    k_total2<<<(388608 + 255) / 256, 256>>>(s1, ctx, att, hf, tot);
    { dim3 g(4, 6, 8); k_gemm_tc<<<g, 256>>>(tot, outw, NOB, part, 384, 250, 1012, 8); }
    k_state2<<<384, 256>>>(part, outb, xr, out + 384 * 4096, 8);

    // ---- decoder ----
    { dim3 g(8, 6, 4); k_gemm_tc<<<g, 256>>>(xr, dfc1w, NOB, part, 384, 512, 250, 4); }
    k_reduce_ln<<<384, 256>>>(part, dfc1b, d1, 384, 512, 4, 1);
    { dim3 g(64, 6, 2); k_gemm_tc<<<g, 256>>>(d1, dfc2w, NOB, h1, 384, 4096, 512, 16); }
    k_reduce_ln<<<384, 256>>>(h1, dfc2b, d2, 384, 4096, 2, 1);
    k_deconv_mma<8,64,32,1,0><<<dim3(192, 4), 256>>>(d2, wgd1, d1b, dd1);
    k_ln_act<<<384, 256>>>(dd1, 8192, 1);
    k_deconv_mma<16,32,16,2,0><<<dim3(384, 4), 256>>>(dd1, wgd2, d2b, dd2);
    k_ln_act<<<384, 256>>>(dd2, 16384, 1);
    k_deconv_mma<32,16,1,2,2><<<dim3(1536, 4), 256>>>(dd2, wgd3, d3b, out);
}